// round 17
// baseline (speedup 1.0000x reference)
#include <cuda_runtime.h>

#define B_  4
#define N_  2048
#define V_  12
#define C_  50
#define P_  16384   /* H*W = 128*128 */
#define RSL 6       /* log2 row stride: 64 floats = 256 B aligned rows */

#define SCAT_BLKS 768          /* (V_*P_)/256 per batch */
#define LIFT_BLKS 512          /* N_/4 per batch        */
#define CHUNK     (SCAT_BLKS + LIFT_BLKS)

// Winner keys, encoded key+1 so 0 == "no winner". Statically zero-initialized;
// lift resets each entry to 0 after reading -> clean state every replay.
__device__ int g_winner[B_ * V_ * N_];

// Per-(bv,pixel) RAW logit rows (50 floats used, 64 stride), written only for
// mask-passing pixels (~7%). Cols 50..63 never written -> always zero.
__device__ float g_feat[((size_t)B_ * V_ * P_) << RSL];   // ~201 MB
// Never written -> always zero. Target for views without a winner.
__device__ float g_zero[1 << RSL];

// Device-side pipeline counters (zero-init; reset by last lift block of each
// batch -> clean every graph replay).
__device__ int g_scnt[B_];   // scatter blocks completed per batch
__device__ int g_fcnt[B_];   // lift blocks completed per batch

__device__ __forceinline__ int ld_acquire(const int* p) {
    int v;
    asm volatile("ld.global.acquire.gpu.b32 %0, [%1];" : "=r"(v) : "l"(p));
    return v;
}

// ONE kernel. Block-id layout per batch b: [768 scatter | 512 lift].
// Scatter blocks: measured R8/R12 body (no early returns), then fence+count.
// Lift blocks: spin until this batch's scatter count == 768 (acquire), then
// the measured R16 lift body. Dependencies point only at earlier block ids ->
// deadlock-free under in-order block dispatch; lifts of batch b overlap
// scatter of batches > b on-chip with no stream/event machinery.
__global__ __launch_bounds__(256) void fused_kernel(
    const float* __restrict__ pred,        // (B,V,C,P)
    const int*   __restrict__ p2p,         // (B,V,P)
    const float* __restrict__ vw,          // (B,V)
    const int*   __restrict__ parts_nb,    // (B,)
    float*       __restrict__ out)         // (B,C,N)
{
    const unsigned FULL = 0xFFFFFFFFu;
    int bid = blockIdx.x;
    int b   = bid / CHUNK;
    int r   = bid - b * CHUNK;

    if (r < SCAT_BLKS) {
        // ---------------- scatter block ----------------
        int t  = r * 256 + threadIdx.x;        // [0, V*P)
        int bv = b * V_ + (t >> 14);           // global view index
        int p  = t & (P_ - 1);

        int point = __ldcs(&p2p[(size_t)bv * P_ + p]);
        int pn    = parts_nb[b];

        const float* base = pred + (size_t)bv * C_ * P_ + p;
        float x[C_];
        float mx = -3.402823466e+38f;
        int   am = 0;
#pragma unroll
        for (int c = 0; c < C_; c++) {
            x[c] = __ldcs(&base[(size_t)c * P_]);
            if (x[c] > mx) { mx = x[c]; am = c; }   // first occurrence
        }

        if (point >= 0 && am >= 1 && am <= pn) {
            float* row = g_feat + (((size_t)bv * P_ + p) << RSL);
            float4* r4 = (float4*)row;
#pragma unroll
            for (int c4 = 0; c4 < C_ / 4; c4++)
                r4[c4] = make_float4(x[4*c4], x[4*c4+1], x[4*c4+2], x[4*c4+3]);
            ((float2*)row)[24] = make_float2(x[48], x[49]);

            int key = am * P_ + p + 1;
            atomicMax(&g_winner[bv * N_ + (point & (N_ - 1))], key);
        }

        // publish: all threads fence their writes, then one count per block
        __threadfence();
        __syncthreads();
        if (threadIdx.x == 0) atomicAdd(&g_scnt[b], 1);

    } else {
        // ---------------- lift block ----------------
        int lb   = r - SCAT_BLKS;              // [0, 512)
        int wid  = threadIdx.x >> 5;
        int lane = threadIdx.x & 31;
        int slot = wid >> 1;                   // 0..3: n within block
        int half = wid & 1;                    // 0/1: views [0,6) or [6,12)
        int n    = lb * 4 + slot;

        __shared__ float s_row[4][V_][64];
        __shared__ float s_par[4][2][64];
        __shared__ float s_cnt[4][2];
        __shared__ float s_acc[C_][5];

        // wait for this batch's scatter to finish (acquire)
        if (threadIdx.x == 0) {
            while (ld_acquire(&g_scnt[b]) < SCAT_BLKS) __nanosleep(200);
        }
        __syncthreads();

        // phase 0
        int key = 0;
        float w = 0.f;
        if (lane < 6) {
            int v = half * 6 + lane;
            int* wp = &g_winner[(b * V_ + v) * N_ + n];
            key = *wp;
            *wp = 0;                           // reset for next graph replay
            w = vw[b * V_ + v];
        }
        unsigned ball = __ballot_sync(FULL, key > 0);
        float cnt = (float)__popc(ball);

        // phase 1: stage this half's 6 rows (12 independent loads)
#pragma unroll
        for (int vl = 0; vl < 6; vl++) {
            int v  = half * 6 + vl;
            int kv = __shfl_sync(FULL, key, vl);
            const float* row = (kv > 0)
                ? g_feat + (((size_t)(b * V_ + v) * P_ + ((kv - 1) & (P_ - 1))) << RSL)
                : g_zero;
            s_row[slot][v][lane]      = __ldg(&row[lane]);
            s_row[slot][v][lane + 32] = __ldg(&row[lane + 32]);
        }

        // phase 2a: batched exps
        float ex0[6], ex1[6], se[6];
#pragma unroll
        for (int vl = 0; vl < 6; vl++) {
            int v = half * 6 + vl;
            ex0[vl] = __expf(s_row[slot][v][lane]);
            ex1[vl] = (lane + 32 < C_) ? __expf(s_row[slot][v][lane + 32]) : 0.f;
            se[vl]  = ex0[vl] + ex1[vl];
        }
        // phase 2b: 6 independent butterflies, stage-interleaved
#pragma unroll
        for (int s = 16; s >= 1; s >>= 1) {
#pragma unroll
            for (int vl = 0; vl < 6; vl++)
                se[vl] += __shfl_xor_sync(FULL, se[vl], s);
        }
        float acc0 = 0.f, acc1 = 0.f;
#pragma unroll
        for (int vl = 0; vl < 6; vl++) {
            int   kv = __shfl_sync(FULL, key, vl);
            float wv = __shfl_sync(FULL, w,   vl);
            float inv = (kv > 0) ? __fdividef(wv, se[vl]) : 0.f;
            acc0 += inv * ex0[vl];
            acc1 += inv * ex1[vl];
        }
        s_par[slot][half][lane]      = acc0;
        s_par[slot][half][lane + 32] = acc1;
        if (lane == 0) s_cnt[slot][half] = cnt;
        __syncthreads();

        if (half == 0) {
            float rdn = __fdividef(1.0f,
                fmaxf(s_cnt[slot][0] + s_cnt[slot][1], 1.f));
            float a0 = (s_par[slot][0][lane]      + s_par[slot][1][lane])      * rdn;
            float a1 = (s_par[slot][0][lane + 32] + s_par[slot][1][lane + 32]) * rdn;
            s_acc[lane][slot] = a0;
            if (lane + 32 < C_) s_acc[lane + 32][slot] = a1;
        }
        __syncthreads();

        int i = threadIdx.x;
        if (i < C_ * 4) {
            int c = i >> 2, j = i & 3;
            out[((size_t)b * C_ + c) * N_ + lb * 4 + j] = s_acc[c][j];
        }

        // retire: last lift block of the batch resets the pipeline counters
        __syncthreads();
        if (threadIdx.x == 0) {
            int old = atomicAdd(&g_fcnt[b], 1);
            if (old == LIFT_BLKS - 1) {
                atomicExch(&g_scnt[b], 0);
                atomicExch(&g_fcnt[b], 0);
            }
        }
    }
}

extern "C" void kernel_launch(void* const* d_in, const int* in_sizes, int n_in,
                              void* d_out, int out_size) {
    // inputs: 0 points (unused), 1 predictions_2d, 2 rendered_pix_to_point,
    //         3 views_weights, 4 parts_nb
    const float* pred     = (const float*)d_in[1];
    const int*   p2p      = (const int*)  d_in[2];
    const float* vw       = (const float*)d_in[3];
    const int*   parts_nb = (const int*)  d_in[4];
    float*       out      = (float*)d_out;

    fused_kernel<<<B_ * CHUNK, 256>>>(pred, p2p, vw, parts_nb, out);
}